// round 9
// baseline (speedup 1.0000x reference)
#include <cuda_runtime.h>
#include <cstdint>

#define BB 64
#define NN 576
#define DD 768
#define KK 1024
#define NT 2
#define ROWS (BB * NN)          // 36864
#define NPAIR (BB * KK)         // 65536
#define OUT_MAIN (NPAIR * NT)   // 131072
#define NV4 (DD / 4)            // 192 float4 per row
#define GRID 296                // 2 blocks/SM x 148 SMs: one co-resident wave
#define RPS 8                   // rows per stage (one per warp)
#define STAGE_F4 (RPS * NV4)    // 1536 float4 = 24 KB per stage
#define NSTAGES_TOT (ROWS / RPS) // 4608

// Per-row projections P[b*N+n] = {z.W0[:,0], z.W0[:,1], z.W1[:,0], z.W1[:,1]}.
__device__ float4 g_P[ROWS];
// Grid barrier counter (generation-counted, graph-replay-safe, never reset).
__device__ unsigned int g_bar;

__device__ __forceinline__ void cp_async16(uint32_t saddr, const void* gaddr) {
    asm volatile("cp.async.cg.shared.global [%0], [%1], 16;"
                 :: "r"(saddr), "l"(gaddr));
}
__device__ __forceinline__ void cp_commit() {
    asm volatile("cp.async.commit_group;" ::: "memory");
}
template <int N> __device__ __forceinline__ void cp_wait() {
    asm volatile("cp.async.wait_group %0;" :: "n"(N) : "memory");
}

// Fused: cp.async double-buffered projection -> grid barrier -> gather.
__global__ __launch_bounds__(256, 2) void partvit_fused_kernel(
    const float* __restrict__ z, const int* __restrict__ idx,
    const float* __restrict__ W, const float* __restrict__ bh,
    float* __restrict__ out, int out_size) {
    // Double-buffered z staging: 2 x 24 KB = 48 KB (static limit exactly).
    __shared__ float4 buf[2][STAGE_F4];

    int tid  = threadIdx.x;
    int lane = tid & 31;
    int w    = tid >> 5;
    int gtid = blockIdx.x * 256 + tid;

    // ---- Prefetch gather inputs (consumed after the barrier) ----
    int2 pr = make_int2(0, 0);
    if (gtid < NPAIR) pr = reinterpret_cast<const int2*>(idx)[gtid];
    float bh0 = bh[0], bh1 = bh[1];

    // ---- Weights in registers: wr[j][c] for d = 4*(lane+32j)+c ----
    float4 wr[6][4];
    #pragma unroll
    for (int j = 0; j < 6; j++) {
        #pragma unroll
        for (int c = 0; c < 4; c++) {
            int d = 4 * (lane + 32 * j) + c;
            wr[j][c] = make_float4(W[2 * d], W[2 * d + 1],
                                   W[2 * (d + DD)], W[2 * (d + DD) + 1]);
        }
    }

    uint32_t sbase = (uint32_t)__cvta_generic_to_shared(buf);

    // ---- Phase 1: pipelined projection ----
    // Stage sid covers rows [sid*8, sid*8+8) = flat float4 range [sid*1536, +1536).
    // Fully coalesced flat copy, 6 x 16B per thread.
    const float4* zf4 = reinterpret_cast<const float4*>(z);

    {
        // prologue: issue stage s=0
        int sid0 = blockIdx.x;
        {
            const float4* src = zf4 + (size_t)sid0 * STAGE_F4;
            uint32_t dst = sbase;                       // buffer 0
            #pragma unroll
            for (int i = 0; i < 6; i++) {
                int t = tid + 256 * i;
                cp_async16(dst + t * 16, src + t);
            }
            cp_commit();
        }

        for (int s = 0;; s++) {
            int sid  = blockIdx.x + s * GRID;
            int nsid = sid + GRID;
            bool has_next = (nsid < NSTAGES_TOT);
            if (has_next) {
                const float4* src = zf4 + (size_t)nsid * STAGE_F4;
                uint32_t dst = sbase + ((s + 1) & 1) * (STAGE_F4 * 16);
                #pragma unroll
                for (int i = 0; i < 6; i++) {
                    int t = tid + 256 * i;
                    cp_async16(dst + t * 16, src + t);
                }
                cp_commit();
                cp_wait<1>();                            // stage s complete
            } else {
                cp_wait<0>();
            }
            __syncthreads();                             // cross-thread visibility

            // compute: warp w owns row sid*8 + w, read from smem
            const float4* zr = &buf[s & 1][w * NV4];
            float ax = 0.f, ay = 0.f, az = 0.f, aw = 0.f;
            #pragma unroll
            for (int j = 0; j < 6; j++) {
                float4 zv = zr[lane + 32 * j];           // conflict-free LDS.128
                ax += zv.x * wr[j][0].x + zv.y * wr[j][1].x
                    + zv.z * wr[j][2].x + zv.w * wr[j][3].x;
                ay += zv.x * wr[j][0].y + zv.y * wr[j][1].y
                    + zv.z * wr[j][2].y + zv.w * wr[j][3].y;
                az += zv.x * wr[j][0].z + zv.y * wr[j][1].z
                    + zv.z * wr[j][2].z + zv.w * wr[j][3].z;
                aw += zv.x * wr[j][0].w + zv.y * wr[j][1].w
                    + zv.z * wr[j][2].w + zv.w * wr[j][3].w;
            }
            #pragma unroll
            for (int off = 16; off; off >>= 1) {
                ax += __shfl_xor_sync(0xffffffffu, ax, off);
                ay += __shfl_xor_sync(0xffffffffu, ay, off);
                az += __shfl_xor_sync(0xffffffffu, az, off);
                aw += __shfl_xor_sync(0xffffffffu, aw, off);
            }
            if (lane == 0) g_P[sid * RPS + w] = make_float4(ax, ay, az, aw);

            if (!has_next) break;
            __syncthreads();   // all warps done reading buf[s&1] before it is
                               // re-targeted at iteration s+1 (writes buf[s&1] at s+2 issue)
        }
    }

    // ---- Device-wide barrier (generation-counted, replay-safe) ----
    __syncthreads();
    if (threadIdx.x == 0) {
        __threadfence();                               // release g_P writes
        unsigned old = atomicAdd(&g_bar, 1u);
        unsigned target = (old / GRID) * GRID + GRID;  // this generation's goal
        unsigned v;
        do {
            asm volatile("ld.global.acquire.gpu.u32 %0, [%1];"
                         : "=r"(v) : "l"(&g_bar));
            if ((int)(v - target) >= 0) break;
            __nanosleep(64);
        } while (true);
    }
    __syncthreads();

    // ---- Phase 2: gather (pair gtid) ----
    if (gtid >= NPAIR) return;
    int b  = gtid >> 10;                               // gtid / KK
    int i0 = min(max(pr.x, 0), NN - 1);
    int i1 = min(max(pr.y, 0), NN - 1);

    float4 p0 = g_P[b * NN + i0];   // pair elem 0 -> W[0:D] halves (.x,.y)
    float4 p1 = g_P[b * NN + i1];   // pair elem 1 -> W[D:2D] halves (.z,.w)

    float2 o;
    o.x = p0.x + p1.z + bh0;
    o.y = p0.y + p1.w + bh1;
    reinterpret_cast<float2*>(out)[gtid] = o;

    // If the harness flattens the (out, indices) tuple, echo indices as f32.
    if (out_size >= OUT_MAIN + 2 * NPAIR) {
        out[OUT_MAIN + 2 * gtid + 0] = (float)pr.x;
        out[OUT_MAIN + 2 * gtid + 1] = (float)pr.y;
    }
}

extern "C" void kernel_launch(void* const* d_in, const int* in_sizes, int n_in,
                              void* d_out, int out_size) {
    const float* z   = (const float*)d_in[0];      // [B, N, D] f32
    const int*   idx = (const int*)d_in[1];        // [B, K, 2] i32
    const float* W   = (const float*)d_in[2];      // [2D, NT] f32
    const float* bh  = (const float*)d_in[3];      // [NT] f32
    float* out = (float*)d_out;

    partvit_fused_kernel<<<GRID, 256>>>(z, idx, W, bh, out, out_size);
}

// round 11
// speedup vs baseline: 1.0742x; 1.0742x over previous
#include <cuda_runtime.h>
#include <cstdint>

#define BB 64
#define NN 576
#define DD 768
#define KK 1024
#define NT 2
#define ROWS (BB * NN)          // 36864
#define NPAIR (BB * KK)         // 65536
#define OUT_MAIN (NPAIR * NT)   // 131072
#define NV4 (DD / 4)            // 192 float4 per row
#define GRID 444                // 3 blocks/SM x 148 SMs: one co-resident wave
#define UROWS 32                // rows per work unit (8 warps x 4 rows)
#define NUNITS (ROWS / UROWS)   // 1152

// Per-row projections P[b*N+n] = {z.W0[:,0], z.W0[:,1], z.W1[:,0], z.W1[:,1]}.
__device__ float4 g_P[ROWS];
// Grid barrier counter (generation-counted, monotonic, graph-replay-safe).
__device__ unsigned int g_bar;
// Dynamic work queue; reset to 0 after the barrier each launch.
__device__ unsigned int g_work;

// z load with L2 evict-last bias via access policy (valid form for v4.f32):
// z (113 MB) nearly fits L2 (126 MB); across graph replays this converts DRAM
// reads into L2 hits.
__device__ __forceinline__ float4 ldg_el(const float4* p, uint64_t pol) {
    float4 v;
    asm volatile("ld.global.nc.L2::cache_hint.v4.f32 {%0,%1,%2,%3}, [%4], %5;"
                 : "=f"(v.x), "=f"(v.y), "=f"(v.z), "=f"(v.w)
                 : "l"(p), "l"(pol));
    return v;
}

// Fused: work-stealing projection -> grid barrier -> gather.
__global__ __launch_bounds__(256, 3) void partvit_fused_kernel(
    const float* __restrict__ z, const int* __restrict__ idx,
    const float* __restrict__ W, const float* __restrict__ bh,
    float* __restrict__ out, int out_size) {
    int tid  = threadIdx.x;
    int lane = tid & 31;
    int w    = tid >> 5;
    int gtid = blockIdx.x * 256 + tid;

    // Evict-last access policy, created once per thread.
    uint64_t pol;
    asm volatile("createpolicy.fractional.L2::evict_last.b64 %0, 1.0;"
                 : "=l"(pol));

    // ---- Prefetch gather inputs (consumed after the barrier) ----
    int2 pr = make_int2(0, 0);
    if (gtid < NPAIR) pr = reinterpret_cast<const int2*>(idx)[gtid];
    float bh0 = bh[0], bh1 = bh[1];

    // ---- Weights: conflict-free component-major smem table (12 KB) ----
    __shared__ float4 Wc[4][NV4];
    __shared__ int s_unit[2];
    for (int f = tid; f < DD; f += 256) {
        int c = f / NV4, i4 = f - c * NV4;
        int d = 4 * i4 + c;
        Wc[c][i4] = make_float4(W[2 * d], W[2 * d + 1],
                                W[2 * (d + DD)], W[2 * (d + DD) + 1]);
    }
    if (tid == 0) s_unit[0] = atomicAdd(&g_work, 1u);
    __syncthreads();

    // ---- Phase 1: projection with dynamic work stealing ----
    int buf = 0;
    for (;;) {
        int u = s_unit[buf];
        if (u >= NUNITS) break;
        if (tid == 0) s_unit[buf ^ 1] = atomicAdd(&g_work, 1u);  // prefetch next

        int row = u * UROWS + w * 4;
        const float4* z4 = reinterpret_cast<const float4*>(z + (size_t)row * DD);

        float4 a0 = {0,0,0,0}, a1 = {0,0,0,0}, a2 = {0,0,0,0}, a3 = {0,0,0,0};
        #pragma unroll 1
        for (int j = 0; j < 6; j++) {
            int i4 = lane + 32 * j;
            float4 z0 = ldg_el(z4 + 0 * NV4 + i4, pol);
            float4 z1 = ldg_el(z4 + 1 * NV4 + i4, pol);
            float4 z2 = ldg_el(z4 + 2 * NV4 + i4, pol);
            float4 z3 = ldg_el(z4 + 3 * NV4 + i4, pol);
            float4 w0 = Wc[0][i4];
            float4 w1 = Wc[1][i4];
            float4 w2 = Wc[2][i4];
            float4 w3 = Wc[3][i4];
            a0.x += z0.x*w0.x + z0.y*w1.x + z0.z*w2.x + z0.w*w3.x;
            a0.y += z0.x*w0.y + z0.y*w1.y + z0.z*w2.y + z0.w*w3.y;
            a0.z += z0.x*w0.z + z0.y*w1.z + z0.z*w2.z + z0.w*w3.z;
            a0.w += z0.x*w0.w + z0.y*w1.w + z0.z*w2.w + z0.w*w3.w;
            a1.x += z1.x*w0.x + z1.y*w1.x + z1.z*w2.x + z1.w*w3.x;
            a1.y += z1.x*w0.y + z1.y*w1.y + z1.z*w2.y + z1.w*w3.y;
            a1.z += z1.x*w0.z + z1.y*w1.z + z1.z*w2.z + z1.w*w3.z;
            a1.w += z1.x*w0.w + z1.y*w1.w + z1.z*w2.w + z1.w*w3.w;
            a2.x += z2.x*w0.x + z2.y*w1.x + z2.z*w2.x + z2.w*w3.x;
            a2.y += z2.x*w0.y + z2.y*w1.y + z2.z*w2.y + z2.w*w3.y;
            a2.z += z2.x*w0.z + z2.y*w1.z + z2.z*w2.z + z2.w*w3.z;
            a2.w += z2.x*w0.w + z2.y*w1.w + z2.z*w2.w + z2.w*w3.w;
            a3.x += z3.x*w0.x + z3.y*w1.x + z3.z*w2.x + z3.w*w3.x;
            a3.y += z3.x*w0.y + z3.y*w1.y + z3.z*w2.y + z3.w*w3.y;
            a3.z += z3.x*w0.z + z3.y*w1.z + z3.z*w2.z + z3.w*w3.z;
            a3.w += z3.x*w0.w + z3.y*w1.w + z3.z*w2.w + z3.w*w3.w;
        }

        #pragma unroll
        for (int off = 16; off; off >>= 1) {
            a0.x += __shfl_xor_sync(0xffffffffu, a0.x, off);
            a0.y += __shfl_xor_sync(0xffffffffu, a0.y, off);
            a0.z += __shfl_xor_sync(0xffffffffu, a0.z, off);
            a0.w += __shfl_xor_sync(0xffffffffu, a0.w, off);
            a1.x += __shfl_xor_sync(0xffffffffu, a1.x, off);
            a1.y += __shfl_xor_sync(0xffffffffu, a1.y, off);
            a1.z += __shfl_xor_sync(0xffffffffu, a1.z, off);
            a1.w += __shfl_xor_sync(0xffffffffu, a1.w, off);
            a2.x += __shfl_xor_sync(0xffffffffu, a2.x, off);
            a2.y += __shfl_xor_sync(0xffffffffu, a2.y, off);
            a2.z += __shfl_xor_sync(0xffffffffu, a2.z, off);
            a2.w += __shfl_xor_sync(0xffffffffu, a2.w, off);
            a3.x += __shfl_xor_sync(0xffffffffu, a3.x, off);
            a3.y += __shfl_xor_sync(0xffffffffu, a3.y, off);
            a3.z += __shfl_xor_sync(0xffffffffu, a3.z, off);
            a3.w += __shfl_xor_sync(0xffffffffu, a3.w, off);
        }
        if (lane == 0) {
            g_P[row + 0] = a0;
            g_P[row + 1] = a1;
            g_P[row + 2] = a2;
            g_P[row + 3] = a3;
        }
        __syncthreads();     // next unit id visible; safe to flip buffers
        buf ^= 1;
    }

    // ---- Device-wide barrier (generation-counted, replay-safe) ----
    __syncthreads();
    if (tid == 0) {
        __threadfence();                               // release g_P writes
        unsigned old = atomicAdd(&g_bar, 1u);
        unsigned target = (old / GRID) * GRID + GRID;  // this generation's goal
        unsigned v;
        do {
            asm volatile("ld.global.acquire.gpu.u32 %0, [%1];"
                         : "=r"(v) : "l"(&g_bar));
            if ((int)(v - target) >= 0) break;
            __nanosleep(64);
        } while (true);
    }
    __syncthreads();

    // Reset the work queue for the next launch/replay (post-barrier: no block
    // can still be fetching; kernel completion orders this before next launch).
    if (blockIdx.x == 0 && tid == 0) g_work = 0u;

    // ---- Phase 2: gather (pair gtid) ----
    if (gtid >= NPAIR) return;
    int b  = gtid >> 10;                               // gtid / KK
    int i0 = min(max(pr.x, 0), NN - 1);
    int i1 = min(max(pr.y, 0), NN - 1);

    float4 p0 = g_P[b * NN + i0];   // pair elem 0 -> W[0:D] halves (.x,.y)
    float4 p1 = g_P[b * NN + i1];   // pair elem 1 -> W[D:2D] halves (.z,.w)

    float2 o;
    o.x = p0.x + p1.z + bh0;
    o.y = p0.y + p1.w + bh1;
    reinterpret_cast<float2*>(out)[gtid] = o;

    // If the harness flattens the (out, indices) tuple, echo indices as f32.
    if (out_size >= OUT_MAIN + 2 * NPAIR) {
        out[OUT_MAIN + 2 * gtid + 0] = (float)pr.x;
        out[OUT_MAIN + 2 * gtid + 1] = (float)pr.y;
    }
}

extern "C" void kernel_launch(void* const* d_in, const int* in_sizes, int n_in,
                              void* d_out, int out_size) {
    const float* z   = (const float*)d_in[0];      // [B, N, D] f32
    const int*   idx = (const int*)d_in[1];        // [B, K, 2] i32
    const float* W   = (const float*)d_in[2];      // [2D, NT] f32
    const float* bh  = (const float*)d_in[3];      // [NT] f32
    float* out = (float*)d_out;

    partvit_fused_kernel<<<GRID, 256>>>(z, idx, W, bh, out, out_size);
}

// round 12
// speedup vs baseline: 1.1844x; 1.1026x over previous
#include <cuda_runtime.h>
#include <cstdint>

#define BB 64
#define NN 576
#define DD 768
#define KK 1024
#define NT 2
#define ROWS (BB * NN)          // 36864
#define NPAIR (BB * KK)         // 65536
#define OUT_MAIN (NPAIR * NT)   // 131072
#define NV4 (DD / 4)            // 192 float4 per row
#define GRID 592                // 4 blocks/SM x 148 SMs: one co-resident wave

// Per-row projections P[b*N+n] = {z.W0[:,0], z.W0[:,1], z.W1[:,0], z.W1[:,1]}.
__device__ float4 g_P[ROWS];
// Grid barrier counter (generation-counted, monotonic, graph-replay-safe).
__device__ unsigned int g_bar;

// Fused: projection (32 warps/SM) -> grid barrier -> gather.
__global__ __launch_bounds__(256, 4) void partvit_fused_kernel(
    const float* __restrict__ z, const int* __restrict__ idx,
    const float* __restrict__ W, const float* __restrict__ bh,
    float* __restrict__ out, int out_size) {
    int tid  = threadIdx.x;
    int lane = tid & 31;
    int gtid = blockIdx.x * 256 + tid;

    // ---- Weights: conflict-free component-major smem table (12 KB) ----
    __shared__ float4 Wc[4][NV4];
    // Prefetched idx pair parked in smem (saves registers across phase 1).
    __shared__ int2 s_pr[256];
    for (int f = tid; f < DD; f += 256) {
        int c = f / NV4, i4 = f - c * NV4;
        int d = 4 * i4 + c;
        Wc[c][i4] = make_float4(W[2 * d], W[2 * d + 1],
                                W[2 * (d + DD)], W[2 * (d + DD) + 1]);
    }
    s_pr[tid] = (gtid < NPAIR) ? reinterpret_cast<const int2*>(idx)[gtid]
                               : make_int2(0, 0);
    __syncthreads();

    // ---- Phase 1: projection, static grid-stride (4 rows per warp-iter) ----
    int gw = gtid >> 5;
    int nw = (GRID * 256) >> 5;   // 4736 warps over 9216 warp-iters (~2 each)

    for (int it = gw; it < ROWS / 4; it += nw) {
        int row = it * 4;
        const float4* z4 = reinterpret_cast<const float4*>(z + (size_t)row * DD);

        float4 a0 = {0,0,0,0}, a1 = {0,0,0,0}, a2 = {0,0,0,0}, a3 = {0,0,0,0};
        #pragma unroll 1
        for (int j = 0; j < 6; j++) {
            int i4 = lane + 32 * j;
            float4 z0 = z4[0 * NV4 + i4];
            float4 z1 = z4[1 * NV4 + i4];
            float4 z2 = z4[2 * NV4 + i4];
            float4 z3 = z4[3 * NV4 + i4];
            float4 w0 = Wc[0][i4];
            float4 w1 = Wc[1][i4];
            float4 w2 = Wc[2][i4];
            float4 w3 = Wc[3][i4];
            a0.x += z0.x*w0.x + z0.y*w1.x + z0.z*w2.x + z0.w*w3.x;
            a0.y += z0.x*w0.y + z0.y*w1.y + z0.z*w2.y + z0.w*w3.y;
            a0.z += z0.x*w0.z + z0.y*w1.z + z0.z*w2.z + z0.w*w3.z;
            a0.w += z0.x*w0.w + z0.y*w1.w + z0.z*w2.w + z0.w*w3.w;
            a1.x += z1.x*w0.x + z1.y*w1.x + z1.z*w2.x + z1.w*w3.x;
            a1.y += z1.x*w0.y + z1.y*w1.y + z1.z*w2.y + z1.w*w3.y;
            a1.z += z1.x*w0.z + z1.y*w1.z + z1.z*w2.z + z1.w*w3.z;
            a1.w += z1.x*w0.w + z1.y*w1.w + z1.z*w2.w + z1.w*w3.w;
            a2.x += z2.x*w0.x + z2.y*w1.x + z2.z*w2.x + z2.w*w3.x;
            a2.y += z2.x*w0.y + z2.y*w1.y + z2.z*w2.y + z2.w*w3.y;
            a2.z += z2.x*w0.z + z2.y*w1.z + z2.z*w2.z + z2.w*w3.z;
            a2.w += z2.x*w0.w + z2.y*w1.w + z2.z*w2.w + z2.w*w3.w;
            a3.x += z3.x*w0.x + z3.y*w1.x + z3.z*w2.x + z3.w*w3.x;
            a3.y += z3.x*w0.y + z3.y*w1.y + z3.z*w2.y + z3.w*w3.y;
            a3.z += z3.x*w0.z + z3.y*w1.z + z3.z*w2.z + z3.w*w3.z;
            a3.w += z3.x*w0.w + z3.y*w1.w + z3.z*w2.w + z3.w*w3.w;
        }

        #pragma unroll
        for (int off = 16; off; off >>= 1) {
            a0.x += __shfl_xor_sync(0xffffffffu, a0.x, off);
            a0.y += __shfl_xor_sync(0xffffffffu, a0.y, off);
            a0.z += __shfl_xor_sync(0xffffffffu, a0.z, off);
            a0.w += __shfl_xor_sync(0xffffffffu, a0.w, off);
            a1.x += __shfl_xor_sync(0xffffffffu, a1.x, off);
            a1.y += __shfl_xor_sync(0xffffffffu, a1.y, off);
            a1.z += __shfl_xor_sync(0xffffffffu, a1.z, off);
            a1.w += __shfl_xor_sync(0xffffffffu, a1.w, off);
            a2.x += __shfl_xor_sync(0xffffffffu, a2.x, off);
            a2.y += __shfl_xor_sync(0xffffffffu, a2.y, off);
            a2.z += __shfl_xor_sync(0xffffffffu, a2.z, off);
            a2.w += __shfl_xor_sync(0xffffffffu, a2.w, off);
            a3.x += __shfl_xor_sync(0xffffffffu, a3.x, off);
            a3.y += __shfl_xor_sync(0xffffffffu, a3.y, off);
            a3.z += __shfl_xor_sync(0xffffffffu, a3.z, off);
            a3.w += __shfl_xor_sync(0xffffffffu, a3.w, off);
        }
        if (lane == 0) {
            g_P[row + 0] = a0;
            g_P[row + 1] = a1;
            g_P[row + 2] = a2;
            g_P[row + 3] = a3;
        }
    }

    // ---- Device-wide barrier (generation-counted, replay-safe) ----
    __syncthreads();
    if (tid == 0) {
        __threadfence();                               // release g_P writes
        unsigned old = atomicAdd(&g_bar, 1u);
        unsigned target = (old / GRID) * GRID + GRID;  // this generation's goal
        unsigned v;
        do {
            asm volatile("ld.global.acquire.gpu.u32 %0, [%1];"
                         : "=r"(v) : "l"(&g_bar));
            if ((int)(v - target) >= 0) break;
            __nanosleep(64);
        } while (true);
    }
    __syncthreads();

    // ---- Phase 2: gather (pair gtid) ----
    if (gtid >= NPAIR) return;
    int2 pr = s_pr[tid];
    float bh0 = bh[0], bh1 = bh[1];                    // L2-hot reload
    int b  = gtid >> 10;                               // gtid / KK
    int i0 = min(max(pr.x, 0), NN - 1);
    int i1 = min(max(pr.y, 0), NN - 1);

    float4 p0 = g_P[b * NN + i0];   // pair elem 0 -> W[0:D] halves (.x,.y)
    float4 p1 = g_P[b * NN + i1];   // pair elem 1 -> W[D:2D] halves (.z,.w)

    float2 o;
    o.x = p0.x + p1.z + bh0;
    o.y = p0.y + p1.w + bh1;
    reinterpret_cast<float2*>(out)[gtid] = o;

    // If the harness flattens the (out, indices) tuple, echo indices as f32.
    if (out_size >= OUT_MAIN + 2 * NPAIR) {
        out[OUT_MAIN + 2 * gtid + 0] = (float)pr.x;
        out[OUT_MAIN + 2 * gtid + 1] = (float)pr.y;
    }
}

extern "C" void kernel_launch(void* const* d_in, const int* in_sizes, int n_in,
                              void* d_out, int out_size) {
    const float* z   = (const float*)d_in[0];      // [B, N, D] f32
    const int*   idx = (const int*)d_in[1];        // [B, K, 2] i32
    const float* W   = (const float*)d_in[2];      // [2D, NT] f32
    const float* bh  = (const float*)d_in[3];      // [NT] f32
    float* out = (float*)d_out;

    partvit_fused_kernel<<<GRID, 256>>>(z, idx, W, bh, out, out_size);
}